// round 3
// baseline (speedup 1.0000x reference)
#include <cuda_runtime.h>
#include <math.h>

// ---------------- problem constants ----------------
#define BATCH   16
#define HH      56
#define WW_     56
#define CDIM    384
#define LTOK    3136          // 56*56
#define NTOK    50176         // BATCH*LTOK == 1024 windows * 49
#define NHEAD   12
#define HD      32
#define WS      7
#define NWIN_T  49            // tokens per window
#define NW_IMG  64            // windows per image (8x8)
#define BWIN    1024          // total windows
#define HID     1536
#define QKVDIM  1152
#define SS      3
#define SCALE   0.17677669529663687f   // 1/sqrt(32)

// ---------------- scratch (device globals; no allocation allowed) ----------
__device__ float g_buf1[(size_t)NTOK * HID];   // qkv (1152 cols used) then mlp hidden (1536)
__device__ float g_buf2[(size_t)NTOK * CDIM];  // xw (LN1+window) then attn-out then h2
__device__ float g_buf3[(size_t)NTOK * CDIM];  // proj output (window layout)
__device__ float g_x2  [(size_t)NTOK * CDIM];  // shortcut + attn branch

// ---------------- LayerNorm (warp per token), optionally fused roll+window --
template<bool WINDOW>
__global__ void ln_kernel(const float* __restrict__ x,
                          const float* __restrict__ gw,
                          const float* __restrict__ bw,
                          float* __restrict__ out)
{
    int warp = threadIdx.x >> 5;
    int lane = threadIdx.x & 31;
    int token = blockIdx.x * 4 + warp;   // NTOK/4 blocks exactly

    int srow;
    if (WINDOW) {
        int wi = token / NWIN_T, n = token % NWIN_T;
        int bb = wi >> 6, wl = wi & 63;
        int wh = wl >> 3, ww = wl & 7;
        int i = n / WS, j = n % WS;
        int hr = (wh * WS + i + SS) % HH;   // roll(-3): src = dst + 3 (mod 56)
        int wr = (ww * WS + j + SS) % WW_;
        srow = bb * LTOK + hr * WW_ + wr;
    } else {
        srow = token;
    }

    const float4* src = (const float4*)(x + (size_t)srow * CDIM);
    float4 v[3];
    float s = 0.f, s2 = 0.f;
#pragma unroll
    for (int t = 0; t < 3; t++) {
        v[t] = src[t * 32 + lane];
        s  += v[t].x + v[t].y + v[t].z + v[t].w;
        s2 += v[t].x*v[t].x + v[t].y*v[t].y + v[t].z*v[t].z + v[t].w*v[t].w;
    }
#pragma unroll
    for (int off = 16; off > 0; off >>= 1) {
        s  += __shfl_xor_sync(0xffffffffu, s,  off);
        s2 += __shfl_xor_sync(0xffffffffu, s2, off);
    }
    const float inv = 1.0f / CDIM;
    float mean = s * inv;
    float var  = s2 * inv - mean * mean;
    float rstd = rsqrtf(var + 1e-5f);

    const float4* g4 = (const float4*)gw;
    const float4* b4 = (const float4*)bw;
    float4* dst = (float4*)(out + (size_t)token * CDIM);
#pragma unroll
    for (int t = 0; t < 3; t++) {
        int c4 = t * 32 + lane;
        float4 g = g4[c4], b = b4[c4], o;
        o.x = (v[t].x - mean) * rstd * g.x + b.x;
        o.y = (v[t].y - mean) * rstd * g.y + b.y;
        o.z = (v[t].z - mean) * rstd * g.z + b.z;
        o.w = (v[t].w - mean) * rstd * g.w + b.w;
        dst[c4] = o;
    }
}

// ---------------- tiled fp32 GEMM: C[M,N] = A[M,K] @ B[K,N] + bias (+epi) ---
// 128x64 tile, 8x4 per thread, BK=16, software-pipelined (register prefetch).
// EPI: 0 = bias, 1 = bias+gelu(exact), 2 = bias+residual
template<int EPI>
__global__ __launch_bounds__(256)
void gemm128(const float* __restrict__ A, const float* __restrict__ B,
             const float* __restrict__ bias, const float* __restrict__ res,
             float* __restrict__ C, int M, int N, int K)
{
    __shared__ float As[16][128];
    __shared__ float Bs[16][64];

    int tid = threadIdx.x;
    int tx = tid & 15;          // N direction: 16 threads * 4 = 64
    int ty = tid >> 4;          // M direction: 16 threads * 8 = 128
    int m0 = blockIdx.y * 128, n0 = blockIdx.x * 64;

    // A-tile load mapping: 128 rows x 16 cols = 512 float4; 2 per thread
    int ar  = tid >> 1;               // 0..127
    int ac4 = (tid & 1) * 8;          // 0 or 8 (two float4s: +0 and +4)
    // B-tile load mapping: 16 rows x 64 cols = 256 float4; 1 per thread
    int bk  = tid >> 4;
    int bn4 = (tid & 15) * 4;

    const float* aptr = A + (size_t)(m0 + ar) * K + ac4;
    const float* bptr = B + (size_t)bk * N + n0 + bn4;

    float acc[8][4] = {};

    // prefetch tile 0 into registers
    float4 pa0 = *(const float4*)(aptr);
    float4 pa1 = *(const float4*)(aptr + 4);
    float4 pb  = *(const float4*)(bptr);

    int nk = K / 16;
    for (int kt = 0; kt < nk; kt++) {
        // store current prefetch to smem
        As[ac4 + 0][ar] = pa0.x;
        As[ac4 + 1][ar] = pa0.y;
        As[ac4 + 2][ar] = pa0.z;
        As[ac4 + 3][ar] = pa0.w;
        As[ac4 + 4][ar] = pa1.x;
        As[ac4 + 5][ar] = pa1.y;
        As[ac4 + 6][ar] = pa1.z;
        As[ac4 + 7][ar] = pa1.w;
        *(float4*)&Bs[bk][bn4] = pb;
        __syncthreads();

        // issue next-tile global loads early (latency overlapped with FMAs)
        if (kt + 1 < nk) {
            const float* an = aptr + (kt + 1) * 16;
            pa0 = *(const float4*)(an);
            pa1 = *(const float4*)(an + 4);
            pb  = *(const float4*)(bptr + (size_t)(kt + 1) * 16 * N);
        }

#pragma unroll
        for (int k = 0; k < 16; k++) {
            float4 av0 = *(const float4*)&As[k][ty * 8];
            float4 av1 = *(const float4*)&As[k][ty * 8 + 4];
            float4 bv  = *(const float4*)&Bs[k][tx * 4];
            float ra[8] = {av0.x, av0.y, av0.z, av0.w, av1.x, av1.y, av1.z, av1.w};
            float rb[4] = {bv.x, bv.y, bv.z, bv.w};
#pragma unroll
            for (int i = 0; i < 8; i++)
#pragma unroll
                for (int j = 0; j < 4; j++)
                    acc[i][j] += ra[i] * rb[j];
        }
        __syncthreads();
    }

    float4 bs = *(const float4*)(bias + n0 + tx * 4);
    float rb[4] = {bs.x, bs.y, bs.z, bs.w};
#pragma unroll
    for (int i = 0; i < 8; i++) {
        int row = m0 + ty * 8 + i;
        float4 o;
        float v[4];
#pragma unroll
        for (int j = 0; j < 4; j++) {
            float val = acc[i][j] + rb[j];
            if (EPI == 1) {
                val = 0.5f * val * (1.0f + erff(val * 0.70710678118654752f));
            }
            v[j] = val;
        }
        if (EPI == 2) {
            float4 r = *(const float4*)(res + (size_t)row * N + n0 + tx * 4);
            v[0] += r.x; v[1] += r.y; v[2] += r.z; v[3] += r.w;
        }
        o.x = v[0]; o.y = v[1]; o.z = v[2]; o.w = v[3];
        *(float4*)(C + (size_t)row * N + n0 + tx * 4) = o;
    }
}

// ---------------- windowed attention: one block per (window, head) ---------
__global__ __launch_bounds__(128)
void attn_kernel(const float* __restrict__ qkv,
                 const float* __restrict__ rpb,   // [169, 12]
                 float* __restrict__ out)         // [NTOK, 384]
{
    int wi = blockIdx.x / NHEAD;
    int h  = blockIdx.x % NHEAD;
    int tid = threadIdx.x;

    __shared__ float q [NWIN_T][33];
    __shared__ float kk[NWIN_T][33];
    __shared__ float vv[NWIN_T][33];
    __shared__ float S [NWIN_T][52];
    __shared__ int   reg[NWIN_T];

    // region ids for the shift mask
    if (tid < NWIN_T) {
        int wl = wi & 63;
        int wh = wl >> 3, ww = wl & 7;
        int hi = wh * WS + tid / WS;
        int wj = ww * WS + tid % WS;
        int rh = hi < 49 ? 0 : (hi < 53 ? 1 : 2);
        int rw = wj < 49 ? 0 : (wj < 53 ? 1 : 2);
        reg[tid] = rh * 3 + rw;
    }

    // load q, k, v tiles ([49,32] each)
    for (int t = tid; t < NWIN_T * 8; t += 128) {
        int n = t >> 3, d4 = (t & 7) * 4;
        const float* base = qkv + (size_t)(wi * NWIN_T + n) * QKVDIM + h * HD + d4;
        float4 a = *(const float4*)(base);
        float4 b = *(const float4*)(base + CDIM);
        float4 c = *(const float4*)(base + 2 * CDIM);
        q [n][d4] = a.x; q [n][d4+1] = a.y; q [n][d4+2] = a.z; q [n][d4+3] = a.w;
        kk[n][d4] = b.x; kk[n][d4+1] = b.y; kk[n][d4+2] = b.z; kk[n][d4+3] = b.w;
        vv[n][d4] = c.x; vv[n][d4+1] = c.y; vv[n][d4+2] = c.z; vv[n][d4+3] = c.w;
    }
    __syncthreads();

    // scores + bias + mask
    for (int t = tid; t < NWIN_T * NWIN_T; t += 128) {
        int i = t / NWIN_T, j = t % NWIN_T;
        float s = 0.f;
#pragma unroll
        for (int d = 0; d < HD; d++) s += q[i][d] * kk[j][d];
        s *= SCALE;
        int dy = i / WS - j / WS;
        int dx = i % WS - j % WS;
        s += rpb[((dy + 6) * 13 + dx + 6) * NHEAD + h];
        if (reg[i] != reg[j]) s -= 100.0f;
        S[i][j] = s;
    }
    __syncthreads();

    // softmax: one thread per row
    if (tid < NWIN_T) {
        float m = -1e30f;
#pragma unroll
        for (int j = 0; j < NWIN_T; j++) m = fmaxf(m, S[tid][j]);
        float sum = 0.f;
#pragma unroll
        for (int j = 0; j < NWIN_T; j++) {
            float e = expf(S[tid][j] - m);
            S[tid][j] = e;
            sum += e;
        }
        float inv = 1.0f / sum;
#pragma unroll
        for (int j = 0; j < NWIN_T; j++) S[tid][j] *= inv;
    }
    __syncthreads();

    // P @ V
    for (int t = tid; t < NWIN_T * HD; t += 128) {
        int i = t >> 5, d = t & 31;
        float s = 0.f;
#pragma unroll
        for (int j = 0; j < NWIN_T; j++) s += S[i][j] * vv[j][d];
        out[(size_t)(wi * NWIN_T + i) * CDIM + h * HD + d] = s;
    }
}

// ---------------- window-reverse + roll-back + residual add ---------------
__global__ void scatter_add(const float* __restrict__ x,
                            const float* __restrict__ ow,   // [NTOK,384] window layout
                            float* __restrict__ x2)
{
    int e = blockIdx.x * 256 + threadIdx.x;   // float4 index; grid sized exactly
    int row = e / 96;
    int c4  = e % 96;
    int b = row / LTOK, p = row % LTOK;
    int hh = p / WW_, ww = p % WW_;
    int hr = (hh + HH - SS) % HH;
    int wr = (ww + WW_ - SS) % WW_;
    int wh = hr / WS, i = hr % WS;
    int wc = wr / WS, j = wr % WS;
    int srow = (b * NW_IMG + wh * 8 + wc) * NWIN_T + i * WS + j;

    float4 a = ((const float4*)x)[(size_t)row * 96 + c4];
    float4 o = ((const float4*)ow)[(size_t)srow * 96 + c4];
    float4 r;
    r.x = a.x + o.x; r.y = a.y + o.y; r.z = a.z + o.z; r.w = a.w + o.w;
    ((float4*)x2)[(size_t)row * 96 + c4] = r;
}

// ---------------- launch ---------------------------------------------------
extern "C" void kernel_launch(void* const* d_in, const int* in_sizes, int n_in,
                              void* d_out, int out_size)
{
    const float* x      = (const float*)d_in[0];
    const float* n1g    = (const float*)d_in[1];
    const float* n1b    = (const float*)d_in[2];
    const float* qkv_w  = (const float*)d_in[3];
    const float* qkv_b  = (const float*)d_in[4];
    const float* rpb    = (const float*)d_in[5];
    const float* proj_w = (const float*)d_in[6];
    const float* proj_b = (const float*)d_in[7];
    const float* n2g    = (const float*)d_in[8];
    const float* n2b    = (const float*)d_in[9];
    const float* fc1_w  = (const float*)d_in[10];
    const float* fc1_b  = (const float*)d_in[11];
    const float* fc2_w  = (const float*)d_in[12];
    const float* fc2_b  = (const float*)d_in[13];
    float* out = (float*)d_out;

    void *p1, *p2, *p3, *p4;
    cudaGetSymbolAddress(&p1, g_buf1);
    cudaGetSymbolAddress(&p2, g_buf2);
    cudaGetSymbolAddress(&p3, g_buf3);
    cudaGetSymbolAddress(&p4, g_x2);
    float* buf1 = (float*)p1;
    float* buf2 = (float*)p2;
    float* buf3 = (float*)p3;
    float* x2   = (float*)p4;

    // 1. LN1 + roll(-3,-3) + window partition  -> buf2 [NTOK, 384]
    ln_kernel<true><<<NTOK / 4, 128>>>(x, n1g, n1b, buf2);

    // 2. QKV GEMM  -> buf1 [NTOK, 1152]
    gemm128<0><<<dim3(QKVDIM / 64, NTOK / 128), 256>>>(buf2, qkv_w, qkv_b, nullptr,
                                                       buf1, NTOK, QKVDIM, CDIM);

    // 3. windowed attention  -> buf2 [NTOK, 384]
    attn_kernel<<<BWIN * NHEAD, 128>>>(buf1, rpb, buf2);

    // 4. proj GEMM  -> buf3 [NTOK, 384]
    gemm128<0><<<dim3(CDIM / 64, NTOK / 128), 256>>>(buf2, proj_w, proj_b, nullptr,
                                                     buf3, NTOK, CDIM, CDIM);

    // 5. window reverse + roll(+3,+3) + residual  -> x2
    scatter_add<<<(NTOK * 96) / 256, 256>>>(x, buf3, x2);

    // 6. LN2  -> buf2
    ln_kernel<false><<<NTOK / 4, 128>>>(x2, n2g, n2b, buf2);

    // 7. fc1 + GELU  -> buf1 [NTOK, 1536]
    gemm128<1><<<dim3(HID / 64, NTOK / 128), 256>>>(buf2, fc1_w, fc1_b, nullptr,
                                                    buf1, NTOK, HID, CDIM);

    // 8. fc2 + residual(x2)  -> out
    gemm128<2><<<dim3(CDIM / 64, NTOK / 128), 256>>>(buf1, fc2_w, fc2_b, x2,
                                                     out, NTOK, CDIM, HID);
}

// round 5
// speedup vs baseline: 1.6312x; 1.6312x over previous
#include <cuda_runtime.h>
#include <math.h>

// ---------------- problem constants ----------------
#define BATCH   16
#define HH      56
#define WW_     56
#define CDIM    384
#define LTOK    3136          // 56*56
#define NTOK    50176         // BATCH*LTOK == 1024 windows * 49
#define NHEAD   12
#define HD      32
#define WS      7
#define NWIN_T  49            // tokens per window
#define NW_IMG  64            // windows per image (8x8)
#define BWIN    1024          // total windows
#define HID     1536
#define QKVDIM  1152
#define SS      3
#define SCALE   0.17677669529663687f   // 1/sqrt(32)

// ---------------- scratch (device globals; no allocation allowed) ----------
__device__ float g_buf1[(size_t)NTOK * HID];   // qkv (1152 cols used) then mlp hidden (1536)
__device__ float g_buf2[(size_t)NTOK * CDIM];  // xw (LN1+window) then attn-out then h2
__device__ float g_buf3[(size_t)NTOK * CDIM];  // proj output (window layout)
__device__ float g_x2  [(size_t)NTOK * CDIM];  // shortcut + attn branch

// ---------------- helpers ---------------------------------------------------
__device__ __forceinline__ unsigned f2tf32(float x) {
    unsigned u;
    asm("cvt.rna.tf32.f32 %0, %1;" : "=r"(u) : "f"(x));
    return u;
}

__device__ __forceinline__ void mma_tf32(float* c, const unsigned* a, const unsigned* b) {
    asm volatile(
        "mma.sync.aligned.m16n8k8.row.col.f32.tf32.tf32.f32 "
        "{%0,%1,%2,%3}, {%4,%5,%6,%7}, {%8,%9}, {%0,%1,%2,%3};\n"
        : "+f"(c[0]), "+f"(c[1]), "+f"(c[2]), "+f"(c[3])
        : "r"(a[0]), "r"(a[1]), "r"(a[2]), "r"(a[3]), "r"(b[0]), "r"(b[1]));
}

// ---------------- LayerNorm (warp per token), optionally fused roll+window --
template<bool WINDOW>
__global__ void ln_kernel(const float* __restrict__ x,
                          const float* __restrict__ gw,
                          const float* __restrict__ bw,
                          float* __restrict__ out)
{
    int warp = threadIdx.x >> 5;
    int lane = threadIdx.x & 31;
    int token = blockIdx.x * 4 + warp;   // NTOK/4 blocks exactly

    int srow;
    if (WINDOW) {
        int wi = token / NWIN_T, n = token % NWIN_T;
        int bb = wi >> 6, wl = wi & 63;
        int wh = wl >> 3, ww = wl & 7;
        int i = n / WS, j = n % WS;
        int hr = (wh * WS + i + SS) % HH;   // roll(-3): src = dst + 3 (mod 56)
        int wr = (ww * WS + j + SS) % WW_;
        srow = bb * LTOK + hr * WW_ + wr;
    } else {
        srow = token;
    }

    const float4* src = (const float4*)(x + (size_t)srow * CDIM);
    float4 v[3];
    float s = 0.f, s2 = 0.f;
#pragma unroll
    for (int t = 0; t < 3; t++) {
        v[t] = src[t * 32 + lane];
        s  += v[t].x + v[t].y + v[t].z + v[t].w;
        s2 += v[t].x*v[t].x + v[t].y*v[t].y + v[t].z*v[t].z + v[t].w*v[t].w;
    }
#pragma unroll
    for (int off = 16; off > 0; off >>= 1) {
        s  += __shfl_xor_sync(0xffffffffu, s,  off);
        s2 += __shfl_xor_sync(0xffffffffu, s2, off);
    }
    const float inv = 1.0f / CDIM;
    float mean = s * inv;
    float var  = s2 * inv - mean * mean;
    float rstd = rsqrtf(var + 1e-5f);

    const float4* g4 = (const float4*)gw;
    const float4* b4 = (const float4*)bw;
    float4* dst = (float4*)(out + (size_t)token * CDIM);
#pragma unroll
    for (int t = 0; t < 3; t++) {
        int c4 = t * 32 + lane;
        float4 g = g4[c4], b = b4[c4], o;
        o.x = (v[t].x - mean) * rstd * g.x + b.x;
        o.y = (v[t].y - mean) * rstd * g.y + b.y;
        o.z = (v[t].z - mean) * rstd * g.z + b.z;
        o.w = (v[t].w - mean) * rstd * g.w + b.w;
        dst[c4] = o;
    }
}

// ---------------- tf32 tensor-core GEMM: C = A@B + bias (+epi) -------------
// 128x64 tile, BK=16, 256 threads = 8 warps (4m x 2n), warp tile 32x32.
// Each warp: 2(m16) x 4(n8) x 2(k8) mma.sync.m16n8k8.tf32 per BK-tile.
// EPI: 0 = bias, 1 = bias+gelu(exact), 2 = bias+residual
template<int EPI>
__global__ __launch_bounds__(256)
void gemm_tc(const float* __restrict__ A, const float* __restrict__ B,
             const float* __restrict__ bias, const float* __restrict__ res,
             float* __restrict__ C, int M, int N, int K)
{
    __shared__ unsigned As[128 * 20];   // [m][k], pad 20 -> conflict-free frags
    __shared__ unsigned Bs[16 * 72];    // [k][n], pad 72 -> conflict-free frags

    int tid  = threadIdx.x;
    int lane = tid & 31;
    int warp = tid >> 5;
    int warpM = warp & 3;        // 0..3 -> m offset 32*warpM
    int warpN = warp >> 2;       // 0..1 -> n offset 32*warpN
    int g = lane >> 2;           // group id (0..7)
    int t = lane & 3;            // thread-in-group (0..3)

    int m0 = blockIdx.y * 128, n0 = blockIdx.x * 64;

    // staging maps
    int ar  = tid >> 1;               // 0..127  (A row)
    int ac4 = (tid & 1) * 8;          // 0 or 8  (A k offset, 8 values)
    int bk  = tid >> 4;               // 0..15   (B k row)
    int bn4 = (tid & 15) * 4;         // B n offset, 4 values

    const float* aptr = A + (size_t)(m0 + ar) * K + ac4;
    const float* bptr = B + (size_t)bk * N + n0 + bn4;

    float acc[2][4][4] = {};

    // prefetch tile 0
    float4 pa0 = *(const float4*)(aptr);
    float4 pa1 = *(const float4*)(aptr + 4);
    float4 pb  = *(const float4*)(bptr);

    int nk = K / 16;
    for (int kt = 0; kt < nk; kt++) {
        // stage (with fp32->tf32 convert) into smem
        unsigned* as = &As[ar * 20 + ac4];
        as[0] = f2tf32(pa0.x); as[1] = f2tf32(pa0.y);
        as[2] = f2tf32(pa0.z); as[3] = f2tf32(pa0.w);
        as[4] = f2tf32(pa1.x); as[5] = f2tf32(pa1.y);
        as[6] = f2tf32(pa1.z); as[7] = f2tf32(pa1.w);
        unsigned* bsm = &Bs[bk * 72 + bn4];
        bsm[0] = f2tf32(pb.x); bsm[1] = f2tf32(pb.y);
        bsm[2] = f2tf32(pb.z); bsm[3] = f2tf32(pb.w);
        __syncthreads();

        // prefetch next tile (latency overlapped with mma)
        if (kt + 1 < nk) {
            const float* an = aptr + (kt + 1) * 16;
            pa0 = *(const float4*)(an);
            pa1 = *(const float4*)(an + 4);
            pb  = *(const float4*)(bptr + (size_t)(kt + 1) * 16 * N);
        }

#pragma unroll
        for (int ks = 0; ks < 2; ks++) {
            unsigned af[2][4];
#pragma unroll
            for (int mt = 0; mt < 2; mt++) {
                int mrow = warpM * 32 + mt * 16 + g;
                af[mt][0] = As[mrow * 20 + ks * 8 + t];
                af[mt][1] = As[(mrow + 8) * 20 + ks * 8 + t];
                af[mt][2] = As[mrow * 20 + ks * 8 + t + 4];
                af[mt][3] = As[(mrow + 8) * 20 + ks * 8 + t + 4];
            }
            unsigned bf[4][2];
#pragma unroll
            for (int nt = 0; nt < 4; nt++) {
                int ncol = warpN * 32 + nt * 8 + g;
                bf[nt][0] = Bs[(ks * 8 + t) * 72 + ncol];
                bf[nt][1] = Bs[(ks * 8 + t + 4) * 72 + ncol];
            }
#pragma unroll
            for (int mt = 0; mt < 2; mt++)
#pragma unroll
                for (int nt = 0; nt < 4; nt++)
                    mma_tf32(acc[mt][nt], af[mt], bf[nt]);
        }
        __syncthreads();
    }

    // epilogue: each (mt, nt) fragment -> rows r0, r0+8, col pair 2t, 2t+1
#pragma unroll
    for (int mt = 0; mt < 2; mt++) {
        int r0 = m0 + warpM * 32 + mt * 16 + g;
#pragma unroll
        for (int nt = 0; nt < 4; nt++) {
            int col = n0 + warpN * 32 + nt * 8 + 2 * t;
            float b0v = bias[col], b1v = bias[col + 1];
            float v[4];
            v[0] = acc[mt][nt][0] + b0v;
            v[1] = acc[mt][nt][1] + b1v;
            v[2] = acc[mt][nt][2] + b0v;
            v[3] = acc[mt][nt][3] + b1v;
            if (EPI == 1) {
#pragma unroll
                for (int e = 0; e < 4; e++)
                    v[e] = 0.5f * v[e] * (1.0f + erff(v[e] * 0.70710678118654752f));
            }
            if (EPI == 2) {
                float2 q0 = *(const float2*)(res + (size_t)r0 * N + col);
                float2 q1 = *(const float2*)(res + (size_t)(r0 + 8) * N + col);
                v[0] += q0.x; v[1] += q0.y; v[2] += q1.x; v[3] += q1.y;
            }
            *(float2*)(C + (size_t)r0 * N + col)       = make_float2(v[0], v[1]);
            *(float2*)(C + (size_t)(r0 + 8) * N + col) = make_float2(v[2], v[3]);
        }
    }
}

// ---------------- windowed attention: one block per (window, head) ---------
__global__ __launch_bounds__(128)
void attn_kernel(const float* __restrict__ qkv,
                 const float* __restrict__ rpb,   // [169, 12]
                 float* __restrict__ out)         // [NTOK, 384]
{
    int wi = blockIdx.x / NHEAD;
    int h  = blockIdx.x % NHEAD;
    int tid = threadIdx.x;

    __shared__ float q [NWIN_T][33];
    __shared__ float kk[NWIN_T][33];
    __shared__ float vv[NWIN_T][33];
    __shared__ float S [NWIN_T][52];
    __shared__ int   reg[NWIN_T];

    // region ids for the shift mask
    if (tid < NWIN_T) {
        int wl = wi & 63;
        int wh = wl >> 3, ww = wl & 7;
        int hi = wh * WS + tid / WS;
        int wj = ww * WS + tid % WS;
        int rh = hi < 49 ? 0 : (hi < 53 ? 1 : 2);
        int rw = wj < 49 ? 0 : (wj < 53 ? 1 : 2);
        reg[tid] = rh * 3 + rw;
    }

    // load q, k, v tiles ([49,32] each)
    for (int t = tid; t < NWIN_T * 8; t += 128) {
        int n = t >> 3, d4 = (t & 7) * 4;
        const float* base = qkv + (size_t)(wi * NWIN_T + n) * QKVDIM + h * HD + d4;
        float4 a = *(const float4*)(base);
        float4 b = *(const float4*)(base + CDIM);
        float4 c = *(const float4*)(base + 2 * CDIM);
        q [n][d4] = a.x; q [n][d4+1] = a.y; q [n][d4+2] = a.z; q [n][d4+3] = a.w;
        kk[n][d4] = b.x; kk[n][d4+1] = b.y; kk[n][d4+2] = b.z; kk[n][d4+3] = b.w;
        vv[n][d4] = c.x; vv[n][d4+1] = c.y; vv[n][d4+2] = c.z; vv[n][d4+3] = c.w;
    }
    __syncthreads();

    // scores + bias + mask
    for (int t = tid; t < NWIN_T * NWIN_T; t += 128) {
        int i = t / NWIN_T, j = t % NWIN_T;
        float s = 0.f;
#pragma unroll
        for (int d = 0; d < HD; d++) s += q[i][d] * kk[j][d];
        s *= SCALE;
        int dy = i / WS - j / WS;
        int dx = i % WS - j % WS;
        s += rpb[((dy + 6) * 13 + dx + 6) * NHEAD + h];
        if (reg[i] != reg[j]) s -= 100.0f;
        S[i][j] = s;
    }
    __syncthreads();

    // softmax: one thread per row
    if (tid < NWIN_T) {
        float m = -1e30f;
#pragma unroll
        for (int j = 0; j < NWIN_T; j++) m = fmaxf(m, S[tid][j]);
        float sum = 0.f;
#pragma unroll
        for (int j = 0; j < NWIN_T; j++) {
            float e = expf(S[tid][j] - m);
            S[tid][j] = e;
            sum += e;
        }
        float inv = 1.0f / sum;
#pragma unroll
        for (int j = 0; j < NWIN_T; j++) S[tid][j] *= inv;
    }
    __syncthreads();

    // P @ V
    for (int t = tid; t < NWIN_T * HD; t += 128) {
        int i = t >> 5, d = t & 31;
        float s = 0.f;
#pragma unroll
        for (int j = 0; j < NWIN_T; j++) s += S[i][j] * vv[j][d];
        out[(size_t)(wi * NWIN_T + i) * CDIM + h * HD + d] = s;
    }
}

// ---------------- window-reverse + roll-back + residual add ---------------
__global__ void scatter_add(const float* __restrict__ x,
                            const float* __restrict__ ow,   // [NTOK,384] window layout
                            float* __restrict__ x2)
{
    int e = blockIdx.x * 256 + threadIdx.x;   // float4 index; grid sized exactly
    int row = e / 96;
    int c4  = e % 96;
    int b = row / LTOK, p = row % LTOK;
    int hh = p / WW_, ww = p % WW_;
    int hr = (hh + HH - SS) % HH;
    int wr = (ww + WW_ - SS) % WW_;
    int wh = hr / WS, i = hr % WS;
    int wc = wr / WS, j = wr % WS;
    int srow = (b * NW_IMG + wh * 8 + wc) * NWIN_T + i * WS + j;

    float4 a = ((const float4*)x)[(size_t)row * 96 + c4];
    float4 o = ((const float4*)ow)[(size_t)srow * 96 + c4];
    float4 r;
    r.x = a.x + o.x; r.y = a.y + o.y; r.z = a.z + o.z; r.w = a.w + o.w;
    ((float4*)x2)[(size_t)row * 96 + c4] = r;
}

// ---------------- launch ---------------------------------------------------
extern "C" void kernel_launch(void* const* d_in, const int* in_sizes, int n_in,
                              void* d_out, int out_size)
{
    const float* x      = (const float*)d_in[0];
    const float* n1g    = (const float*)d_in[1];
    const float* n1b    = (const float*)d_in[2];
    const float* qkv_w  = (const float*)d_in[3];
    const float* qkv_b  = (const float*)d_in[4];
    const float* rpb    = (const float*)d_in[5];
    const float* proj_w = (const float*)d_in[6];
    const float* proj_b = (const float*)d_in[7];
    const float* n2g    = (const float*)d_in[8];
    const float* n2b    = (const float*)d_in[9];
    const float* fc1_w  = (const float*)d_in[10];
    const float* fc1_b  = (const float*)d_in[11];
    const float* fc2_w  = (const float*)d_in[12];
    const float* fc2_b  = (const float*)d_in[13];
    float* out = (float*)d_out;

    void *p1, *p2, *p3, *p4;
    cudaGetSymbolAddress(&p1, g_buf1);
    cudaGetSymbolAddress(&p2, g_buf2);
    cudaGetSymbolAddress(&p3, g_buf3);
    cudaGetSymbolAddress(&p4, g_x2);
    float* buf1 = (float*)p1;
    float* buf2 = (float*)p2;
    float* buf3 = (float*)p3;
    float* x2   = (float*)p4;

    // 1. LN1 + roll(-3,-3) + window partition  -> buf2 [NTOK, 384]
    ln_kernel<true><<<NTOK / 4, 128>>>(x, n1g, n1b, buf2);

    // 2. QKV GEMM  -> buf1 [NTOK, 1152]
    gemm_tc<0><<<dim3(QKVDIM / 64, NTOK / 128), 256>>>(buf2, qkv_w, qkv_b, nullptr,
                                                       buf1, NTOK, QKVDIM, CDIM);

    // 3. windowed attention  -> buf2 [NTOK, 384]
    attn_kernel<<<BWIN * NHEAD, 128>>>(buf1, rpb, buf2);

    // 4. proj GEMM  -> buf3 [NTOK, 384]
    gemm_tc<0><<<dim3(CDIM / 64, NTOK / 128), 256>>>(buf2, proj_w, proj_b, nullptr,
                                                     buf3, NTOK, CDIM, CDIM);

    // 5. window reverse + roll(+3,+3) + residual  -> x2
    scatter_add<<<(NTOK * 96) / 256, 256>>>(x, buf3, x2);

    // 6. LN2  -> buf2
    ln_kernel<false><<<NTOK / 4, 128>>>(x2, n2g, n2b, buf2);

    // 7. fc1 + GELU  -> buf1 [NTOK, 1536]
    gemm_tc<1><<<dim3(HID / 64, NTOK / 128), 256>>>(buf2, fc1_w, fc1_b, nullptr,
                                                    buf1, NTOK, HID, CDIM);

    // 8. fc2 + residual(x2)  -> out
    gemm_tc<2><<<dim3(CDIM / 64, NTOK / 128), 256>>>(buf1, fc2_w, fc2_b, x2,
                                                     out, NTOK, CDIM, HID);
}

// round 9
// speedup vs baseline: 2.0812x; 1.2758x over previous
#include <cuda_runtime.h>
#include <math.h>

// ---------------- problem constants ----------------
#define BATCH   16
#define HH      56
#define WW_     56
#define CDIM    384
#define LTOK    3136          // 56*56
#define NTOK    50176         // BATCH*LTOK == 1024 windows * 49
#define NHEAD   12
#define HD      32
#define WS      7
#define NWIN_T  49            // tokens per window
#define NW_IMG  64            // windows per image (8x8)
#define BWIN    1024          // total windows
#define HID     1536
#define QKVDIM  1152
#define SS      3
#define SCALE   0.17677669529663687f   // 1/sqrt(32)

// ---------------- scratch (device globals; no allocation allowed) ----------
__device__ float g_buf1[(size_t)NTOK * HID];   // qkv (1152 cols used) then mlp hidden (1536)
__device__ float g_buf2[(size_t)NTOK * CDIM];  // xw (LN1+window) then attn-out then h2
__device__ float g_buf3[(size_t)NTOK * CDIM];  // proj output (window layout)
__device__ float g_x2  [(size_t)NTOK * CDIM];  // shortcut + attn branch

// ---------------- helpers ---------------------------------------------------
__device__ __forceinline__ unsigned f2tf32(float x) {
    unsigned u;
    asm("cvt.rna.tf32.f32 %0, %1;" : "=r"(u) : "f"(x));
    return u;
}

__device__ __forceinline__ void mma_tf32(float* c, const unsigned* a, const unsigned* b) {
    asm volatile(
        "mma.sync.aligned.m16n8k8.row.col.f32.tf32.tf32.f32 "
        "{%0,%1,%2,%3}, {%4,%5,%6,%7}, {%8,%9}, {%0,%1,%2,%3};\n"
        : "+f"(c[0]), "+f"(c[1]), "+f"(c[2]), "+f"(c[3])
        : "r"(a[0]), "r"(a[1]), "r"(a[2]), "r"(a[3]), "r"(b[0]), "r"(b[1]));
}

// ---------------- LayerNorm (warp per token), optionally fused roll+window --
template<bool WINDOW>
__global__ void ln_kernel(const float* __restrict__ x,
                          const float* __restrict__ gw,
                          const float* __restrict__ bw,
                          float* __restrict__ out)
{
    int warp = threadIdx.x >> 5;
    int lane = threadIdx.x & 31;
    int token = blockIdx.x * 4 + warp;   // NTOK/4 blocks exactly

    int srow;
    if (WINDOW) {
        int wi = token / NWIN_T, n = token % NWIN_T;
        int bb = wi >> 6, wl = wi & 63;
        int wh = wl >> 3, ww = wl & 7;
        int i = n / WS, j = n % WS;
        int hr = (wh * WS + i + SS) % HH;   // roll(-3): src = dst + 3 (mod 56)
        int wr = (ww * WS + j + SS) % WW_;
        srow = bb * LTOK + hr * WW_ + wr;
    } else {
        srow = token;
    }

    const float4* src = (const float4*)(x + (size_t)srow * CDIM);
    float4 v[3];
    float s = 0.f, s2 = 0.f;
#pragma unroll
    for (int t = 0; t < 3; t++) {
        v[t] = src[t * 32 + lane];
        s  += v[t].x + v[t].y + v[t].z + v[t].w;
        s2 += v[t].x*v[t].x + v[t].y*v[t].y + v[t].z*v[t].z + v[t].w*v[t].w;
    }
#pragma unroll
    for (int off = 16; off > 0; off >>= 1) {
        s  += __shfl_xor_sync(0xffffffffu, s,  off);
        s2 += __shfl_xor_sync(0xffffffffu, s2, off);
    }
    const float inv = 1.0f / CDIM;
    float mean = s * inv;
    float var  = s2 * inv - mean * mean;
    float rstd = rsqrtf(var + 1e-5f);

    const float4* g4 = (const float4*)gw;
    const float4* b4 = (const float4*)bw;
    float4* dst = (float4*)(out + (size_t)token * CDIM);
#pragma unroll
    for (int t = 0; t < 3; t++) {
        int c4 = t * 32 + lane;
        float4 g = g4[c4], b = b4[c4], o;
        o.x = (v[t].x - mean) * rstd * g.x + b.x;
        o.y = (v[t].y - mean) * rstd * g.y + b.y;
        o.z = (v[t].z - mean) * rstd * g.z + b.z;
        o.w = (v[t].w - mean) * rstd * g.w + b.w;
        dst[c4] = o;
    }
}

// ---------------- tf32 tensor-core GEMM: C = A@B + bias (+epi) -------------
// 128x128 block tile, BK=16, double-buffered smem, 256 threads = 8 warps
// (2M x 4N), warp tile 64x32: 4(m16) x 4(n8) x 2(k8) mma per BK-tile.
// EPI: 0 = bias, 1 = bias+gelu(exact), 2 = bias+residual
#define APAD 20
#define BPAD 136
#define ASZ  (128 * APAD)
#define BSZ  (16 * BPAD)

template<int EPI>
__global__ __launch_bounds__(256, 2)
void gemm_tc(const float* __restrict__ A, const float* __restrict__ B,
             const float* __restrict__ bias, const float* __restrict__ res,
             float* __restrict__ C, int M, int N, int K)
{
    __shared__ unsigned As[2 * ASZ];   // [buf][m][k] pad 20
    __shared__ unsigned Bs[2 * BSZ];   // [buf][k][n] pad 136

    int tid  = threadIdx.x;
    int lane = tid & 31;
    int warp = tid >> 5;
    int warpM = warp >> 2;       // 0..1 -> m offset 64*warpM
    int warpN = warp & 3;        // 0..3 -> n offset 32*warpN
    int g = lane >> 2;           // group id (0..7)
    int t = lane & 3;            // thread-in-group (0..3)

    int m0 = blockIdx.y * 128, n0 = blockIdx.x * 128;

    // staging maps
    int ar  = tid >> 1;               // 0..127  (A row)
    int ac4 = (tid & 1) * 8;          // 0 or 8  (A k offset, 8 values)
    int bk  = tid >> 4;               // 0..15   (B k row)
    int bn4 = (tid & 15) * 4;         // B n offset (first half; second at +64)

    const float* aptr = A + (size_t)(m0 + ar) * K + ac4;
    const float* bptr = B + (size_t)bk * N + n0 + bn4;

    float acc[4][4][4] = {};

    // prefetch tile 0
    float4 pa0 = *(const float4*)(aptr);
    float4 pa1 = *(const float4*)(aptr + 4);
    float4 pb0 = *(const float4*)(bptr);
    float4 pb1 = *(const float4*)(bptr + 64);

    // stage tile 0 into buffer 0
    {
        unsigned* as = &As[ar * APAD + ac4];
        as[0] = f2tf32(pa0.x); as[1] = f2tf32(pa0.y);
        as[2] = f2tf32(pa0.z); as[3] = f2tf32(pa0.w);
        as[4] = f2tf32(pa1.x); as[5] = f2tf32(pa1.y);
        as[6] = f2tf32(pa1.z); as[7] = f2tf32(pa1.w);
        unsigned* bsm = &Bs[bk * BPAD + bn4];
        bsm[0]  = f2tf32(pb0.x); bsm[1]  = f2tf32(pb0.y);
        bsm[2]  = f2tf32(pb0.z); bsm[3]  = f2tf32(pb0.w);
        bsm[64] = f2tf32(pb1.x); bsm[65] = f2tf32(pb1.y);
        bsm[66] = f2tf32(pb1.z); bsm[67] = f2tf32(pb1.w);
    }
    __syncthreads();

    int nk = K / 16;
    for (int kt = 0; kt < nk; kt++) {
        int p = kt & 1;
        const unsigned* Ab = &As[p * ASZ];
        const unsigned* Bb = &Bs[p * BSZ];

        // issue next-tile global loads (latency overlapped with mma below)
        if (kt + 1 < nk) {
            const float* an = aptr + (kt + 1) * 16;
            pa0 = *(const float4*)(an);
            pa1 = *(const float4*)(an + 4);
            const float* bn = bptr + (size_t)(kt + 1) * 16 * N;
            pb0 = *(const float4*)(bn);
            pb1 = *(const float4*)(bn + 64);
        }

#pragma unroll
        for (int ks = 0; ks < 2; ks++) {
            unsigned af[4][4];
#pragma unroll
            for (int mt = 0; mt < 4; mt++) {
                int mrow = warpM * 64 + mt * 16 + g;
                af[mt][0] = Ab[mrow * APAD + ks * 8 + t];
                af[mt][1] = Ab[(mrow + 8) * APAD + ks * 8 + t];
                af[mt][2] = Ab[mrow * APAD + ks * 8 + t + 4];
                af[mt][3] = Ab[(mrow + 8) * APAD + ks * 8 + t + 4];
            }
            unsigned bf[4][2];
#pragma unroll
            for (int nt = 0; nt < 4; nt++) {
                int ncol = warpN * 32 + nt * 8 + g;
                bf[nt][0] = Bb[(ks * 8 + t) * BPAD + ncol];
                bf[nt][1] = Bb[(ks * 8 + t + 4) * BPAD + ncol];
            }
#pragma unroll
            for (int mt = 0; mt < 4; mt++)
#pragma unroll
                for (int nt = 0; nt < 4; nt++)
                    mma_tf32(acc[mt][nt], af[mt], bf[nt]);
        }

        // stage next tile into the other buffer (overlaps tensor work)
        if (kt + 1 < nk) {
            unsigned* as = &As[(1 - p) * ASZ + ar * APAD + ac4];
            as[0] = f2tf32(pa0.x); as[1] = f2tf32(pa0.y);
            as[2] = f2tf32(pa0.z); as[3] = f2tf32(pa0.w);
            as[4] = f2tf32(pa1.x); as[5] = f2tf32(pa1.y);
            as[6] = f2tf32(pa1.z); as[7] = f2tf32(pa1.w);
            unsigned* bsm = &Bs[(1 - p) * BSZ + bk * BPAD + bn4];
            bsm[0]  = f2tf32(pb0.x); bsm[1]  = f2tf32(pb0.y);
            bsm[2]  = f2tf32(pb0.z); bsm[3]  = f2tf32(pb0.w);
            bsm[64] = f2tf32(pb1.x); bsm[65] = f2tf32(pb1.y);
            bsm[66] = f2tf32(pb1.z); bsm[67] = f2tf32(pb1.w);
        }
        __syncthreads();
    }

    // epilogue: each (mt, nt) fragment -> rows r0, r0+8, col pair 2t, 2t+1
#pragma unroll
    for (int mt = 0; mt < 4; mt++) {
        int r0 = m0 + warpM * 64 + mt * 16 + g;
#pragma unroll
        for (int nt = 0; nt < 4; nt++) {
            int col = n0 + warpN * 32 + nt * 8 + 2 * t;
            float b0v = bias[col], b1v = bias[col + 1];
            float v[4];
            v[0] = acc[mt][nt][0] + b0v;
            v[1] = acc[mt][nt][1] + b1v;
            v[2] = acc[mt][nt][2] + b0v;
            v[3] = acc[mt][nt][3] + b1v;
            if (EPI == 1) {
#pragma unroll
                for (int e = 0; e < 4; e++)
                    v[e] = 0.5f * v[e] * (1.0f + erff(v[e] * 0.70710678118654752f));
            }
            if (EPI == 2) {
                float2 q0 = *(const float2*)(res + (size_t)r0 * N + col);
                float2 q1 = *(const float2*)(res + (size_t)(r0 + 8) * N + col);
                v[0] += q0.x; v[1] += q0.y; v[2] += q1.x; v[3] += q1.y;
            }
            *(float2*)(C + (size_t)r0 * N + col)       = make_float2(v[0], v[1]);
            *(float2*)(C + (size_t)(r0 + 8) * N + col) = make_float2(v[2], v[3]);
        }
    }
}

// ---------------- windowed attention: one block per (window, head) ---------
__global__ __launch_bounds__(128)
void attn_kernel(const float* __restrict__ qkv,
                 const float* __restrict__ rpb,   // [169, 12]
                 float* __restrict__ out)         // [NTOK, 384]
{
    int wi = blockIdx.x / NHEAD;
    int h  = blockIdx.x % NHEAD;
    int tid = threadIdx.x;

    __shared__ float q [NWIN_T][33];
    __shared__ float kk[NWIN_T][33];
    __shared__ float vv[NWIN_T][33];
    __shared__ float S [NWIN_T][52];
    __shared__ int   reg[NWIN_T];

    // region ids for the shift mask
    if (tid < NWIN_T) {
        int wl = wi & 63;
        int wh = wl >> 3, ww = wl & 7;
        int hi = wh * WS + tid / WS;
        int wj = ww * WS + tid % WS;
        int rh = hi < 49 ? 0 : (hi < 53 ? 1 : 2);
        int rw = wj < 49 ? 0 : (wj < 53 ? 1 : 2);
        reg[tid] = rh * 3 + rw;
    }

    // load q, k, v tiles ([49,32] each)
    for (int t = tid; t < NWIN_T * 8; t += 128) {
        int n = t >> 3, d4 = (t & 7) * 4;
        const float* base = qkv + (size_t)(wi * NWIN_T + n) * QKVDIM + h * HD + d4;
        float4 a = *(const float4*)(base);
        float4 b = *(const float4*)(base + CDIM);
        float4 c = *(const float4*)(base + 2 * CDIM);
        q [n][d4] = a.x; q [n][d4+1] = a.y; q [n][d4+2] = a.z; q [n][d4+3] = a.w;
        kk[n][d4] = b.x; kk[n][d4+1] = b.y; kk[n][d4+2] = b.z; kk[n][d4+3] = b.w;
        vv[n][d4] = c.x; vv[n][d4+1] = c.y; vv[n][d4+2] = c.z; vv[n][d4+3] = c.w;
    }
    __syncthreads();

    // scores + bias + mask
    for (int t = tid; t < NWIN_T * NWIN_T; t += 128) {
        int i = t / NWIN_T, j = t % NWIN_T;
        float s = 0.f;
#pragma unroll
        for (int d = 0; d < HD; d++) s += q[i][d] * kk[j][d];
        s *= SCALE;
        int dy = i / WS - j / WS;
        int dx = i % WS - j % WS;
        s += rpb[((dy + 6) * 13 + dx + 6) * NHEAD + h];
        if (reg[i] != reg[j]) s -= 100.0f;
        S[i][j] = s;
    }
    __syncthreads();

    // softmax: one thread per row
    if (tid < NWIN_T) {
        float m = -1e30f;
#pragma unroll
        for (int j = 0; j < NWIN_T; j++) m = fmaxf(m, S[tid][j]);
        float sum = 0.f;
#pragma unroll
        for (int j = 0; j < NWIN_T; j++) {
            float e = expf(S[tid][j] - m);
            S[tid][j] = e;
            sum += e;
        }
        float inv = 1.0f / sum;
#pragma unroll
        for (int j = 0; j < NWIN_T; j++) S[tid][j] *= inv;
    }
    __syncthreads();

    // P @ V
    for (int t = tid; t < NWIN_T * HD; t += 128) {
        int i = t >> 5, d = t & 31;
        float s = 0.f;
#pragma unroll
        for (int j = 0; j < NWIN_T; j++) s += S[i][j] * vv[j][d];
        out[(size_t)(wi * NWIN_T + i) * CDIM + h * HD + d] = s;
    }
}

// ---------------- window-reverse + roll-back + residual add ---------------
__global__ void scatter_add(const float* __restrict__ x,
                            const float* __restrict__ ow,   // [NTOK,384] window layout
                            float* __restrict__ x2)
{
    int e = blockIdx.x * 256 + threadIdx.x;   // float4 index; grid sized exactly
    int row = e / 96;
    int c4  = e % 96;
    int b = row / LTOK, p = row % LTOK;
    int hh = p / WW_, ww = p % WW_;
    int hr = (hh + HH - SS) % HH;
    int wr = (ww + WW_ - SS) % WW_;
    int wh = hr / WS, i = hr % WS;
    int wc = wr / WS, j = wr % WS;
    int srow = (b * NW_IMG + wh * 8 + wc) * NWIN_T + i * WS + j;

    float4 a = ((const float4*)x)[(size_t)row * 96 + c4];
    float4 o = ((const float4*)ow)[(size_t)srow * 96 + c4];
    float4 r;
    r.x = a.x + o.x; r.y = a.y + o.y; r.z = a.z + o.z; r.w = a.w + o.w;
    ((float4*)x2)[(size_t)row * 96 + c4] = r;
}

// ---------------- launch ---------------------------------------------------
extern "C" void kernel_launch(void* const* d_in, const int* in_sizes, int n_in,
                              void* d_out, int out_size)
{
    const float* x      = (const float*)d_in[0];
    const float* n1g    = (const float*)d_in[1];
    const float* n1b    = (const float*)d_in[2];
    const float* qkv_w  = (const float*)d_in[3];
    const float* qkv_b  = (const float*)d_in[4];
    const float* rpb    = (const float*)d_in[5];
    const float* proj_w = (const float*)d_in[6];
    const float* proj_b = (const float*)d_in[7];
    const float* n2g    = (const float*)d_in[8];
    const float* n2b    = (const float*)d_in[9];
    const float* fc1_w  = (const float*)d_in[10];
    const float* fc1_b  = (const float*)d_in[11];
    const float* fc2_w  = (const float*)d_in[12];
    const float* fc2_b  = (const float*)d_in[13];
    float* out = (float*)d_out;

    void *p1, *p2, *p3, *p4;
    cudaGetSymbolAddress(&p1, g_buf1);
    cudaGetSymbolAddress(&p2, g_buf2);
    cudaGetSymbolAddress(&p3, g_buf3);
    cudaGetSymbolAddress(&p4, g_x2);
    float* buf1 = (float*)p1;
    float* buf2 = (float*)p2;
    float* buf3 = (float*)p3;
    float* x2   = (float*)p4;

    // 1. LN1 + roll(-3,-3) + window partition  -> buf2 [NTOK, 384]
    ln_kernel<true><<<NTOK / 4, 128>>>(x, n1g, n1b, buf2);

    // 2. QKV GEMM  -> buf1 [NTOK, 1152]
    gemm_tc<0><<<dim3(QKVDIM / 128, NTOK / 128), 256>>>(buf2, qkv_w, qkv_b, nullptr,
                                                        buf1, NTOK, QKVDIM, CDIM);

    // 3. windowed attention  -> buf2 [NTOK, 384]
    attn_kernel<<<BWIN * NHEAD, 128>>>(buf1, rpb, buf2);

    // 4. proj GEMM  -> buf3 [NTOK, 384]
    gemm_tc<0><<<dim3(CDIM / 128, NTOK / 128), 256>>>(buf2, proj_w, proj_b, nullptr,
                                                      buf3, NTOK, CDIM, CDIM);

    // 5. window reverse + roll(+3,+3) + residual  -> x2
    scatter_add<<<(NTOK * 96) / 256, 256>>>(x, buf3, x2);

    // 6. LN2  -> buf2
    ln_kernel<false><<<NTOK / 4, 128>>>(x2, n2g, n2b, buf2);

    // 7. fc1 + GELU  -> buf1 [NTOK, 1536]
    gemm_tc<1><<<dim3(HID / 128, NTOK / 128), 256>>>(buf2, fc1_w, fc1_b, nullptr,
                                                     buf1, NTOK, HID, CDIM);

    // 8. fc2 + residual(x2)  -> out
    gemm_tc<2><<<dim3(CDIM / 128, NTOK / 128), 256>>>(buf1, fc2_w, fc2_b, x2,
                                                      out, NTOK, CDIM, HID);
}